// round 12
// baseline (speedup 1.0000x reference)
#include <cuda_runtime.h>
#include <cstdint>

#define BB 8
#define TT 2048
#define CC 1024
#define HH 128
#define BT (BB*TT)
#define SCALE 0.08838834764831845f

#define PX_LD 36     // proj sX row stride (32 k + 4 pad)
#define PW_LD 136    // proj sW row stride (128 n + 8 pad)
#define LDT 132      // flash K/V row stride (128 + 4)

// q/k/v scratch stored as tf32 bit patterns (static device mem: allowed)
__device__ uint32_t g_q[BT * HH];
__device__ uint32_t g_k[BT * HH];
__device__ uint32_t g_v[BT * HH];

__device__ __forceinline__ uint32_t f2tf(float x) {
    uint32_t r;
    asm("cvt.rna.tf32.f32 %0, %1;" : "=r"(r) : "f"(x));
    return r;
}

// D += A*B, m16n8k8, A row-major 16x8 tf32, B col-major 8x8 tf32, fp32 accum
__device__ __forceinline__ void mma8(float* c, uint32_t a0, uint32_t a1,
                                     uint32_t a2, uint32_t a3,
                                     uint32_t b0, uint32_t b1) {
    asm volatile(
        "mma.sync.aligned.m16n8k8.row.col.f32.tf32.tf32.f32 "
        "{%0,%1,%2,%3},{%4,%5,%6,%7},{%8,%9},{%0,%1,%2,%3};"
        : "+f"(c[0]), "+f"(c[1]), "+f"(c[2]), "+f"(c[3])
        : "r"(a0), "r"(a1), "r"(a2), "r"(a3), "r"(b0), "r"(b1));
}

// ---------------------------------------------------------------------------
// Projection v2: q|k|v = tf32(x @ [Wq|Wk|Wv]) in ONE pass over x.
// Block = 64 rows x 384 cols (3 mats), 256 thr, 8 warps = 2 rg x 4 wc.
// Warp tile 32 rows x 96 cols. x DRAM traffic: 64 MB (was 192 MB).
// smem 61440 B -> DYNAMIC (over the 48 KB static limit).
// ---------------------------------------------------------------------------
#define PROJ_SMEM_WORDS (64 * PX_LD + 3 * 32 * PW_LD)   // 15360 words = 61440 B

__global__ __launch_bounds__(256) void proj_kernel(
    const float* __restrict__ x,
    const float* __restrict__ Wk,
    const float* __restrict__ Wq,
    const float* __restrict__ Wv)
{
    extern __shared__ uint32_t psm[];
    uint32_t* sX = psm;                     // 64 rows x 32 k (PX_LD stride)
    uint32_t* sW = psm + 64 * PX_LD;        // 3 mats x 32 k x 128 n (PW_LD)

    const int row0 = blockIdx.x * 64;
    const int tid  = threadIdx.x;
    const int wid  = tid >> 5, lane = tid & 31;
    const int g = lane >> 2, q = lane & 3;
    const int rg = wid & 1;          // row group: rows rg*32..+31
    const int wc = wid >> 1;         // col group: cols wc*96..+95

    float acc[2][12][4];
#pragma unroll
    for (int mt = 0; mt < 2; mt++)
#pragma unroll
        for (int nt = 0; nt < 12; nt++)
#pragma unroll
            for (int i = 0; i < 4; i++) acc[mt][nt][i] = 0.f;

    for (int k0 = 0; k0 < CC; k0 += 32) {
        // x tile 64x32 -> tf32 smem (512 uint4, 2/thread)
#pragma unroll
        for (int t = 0; t < 2; t++) {
            int idx = tid + t * 256;
            int r = idx >> 3, c4 = (idx & 7) * 4;
            float4 xv = *(const float4*)(x + (size_t)(row0 + r) * CC + k0 + c4);
            uint4 u = make_uint4(f2tf(xv.x), f2tf(xv.y), f2tf(xv.z), f2tf(xv.w));
            *(uint4*)&sX[r * PX_LD + c4] = u;
        }
        // three W tiles 32x128 each (3072 uint4, 12/thread)
#pragma unroll
        for (int m = 0; m < 3; m++) {
            const float* Wm = (m == 0) ? Wq : (m == 1) ? Wk : Wv;
#pragma unroll
            for (int tt = 0; tt < 4; tt++) {
                int idx = tid + tt * 256;
                int r = idx >> 5, c4 = (idx & 31) * 4;
                float4 wv = *(const float4*)(Wm + (size_t)(k0 + r) * HH + c4);
                uint4 u = make_uint4(f2tf(wv.x), f2tf(wv.y), f2tf(wv.z), f2tf(wv.w));
                *(uint4*)&sW[(m * 32 + r) * PW_LD + c4] = u;
            }
        }
        __syncthreads();

#pragma unroll
        for (int ks = 0; ks < 4; ks++) {
            int kk = ks * 8;
            uint32_t a[2][4];
#pragma unroll
            for (int mt = 0; mt < 2; mt++) {
                int mr = rg * 32 + mt * 16;
                a[mt][0] = sX[(mr + g)     * PX_LD + kk + q];
                a[mt][1] = sX[(mr + g + 8) * PX_LD + kk + q];
                a[mt][2] = sX[(mr + g)     * PX_LD + kk + q + 4];
                a[mt][3] = sX[(mr + g + 8) * PX_LD + kk + q + 4];
            }
#pragma unroll
            for (int nt = 0; nt < 12; nt++) {
                int cg  = wc * 96 + nt * 8;
                int mat = cg >> 7;
                int col = cg & 127;
                uint32_t b0 = sW[(mat * 32 + kk + q)     * PW_LD + col + g];
                uint32_t b1 = sW[(mat * 32 + kk + q + 4) * PW_LD + col + g];
                mma8(acc[0][nt], a[0][0], a[0][1], a[0][2], a[0][3], b0, b1);
                mma8(acc[1][nt], a[1][0], a[1][1], a[1][2], a[1][3], b0, b1);
            }
        }
        __syncthreads();
    }

#pragma unroll
    for (int mt = 0; mt < 2; mt++)
#pragma unroll
        for (int nt = 0; nt < 12; nt++) {
            int cg  = wc * 96 + nt * 8;
            int mat = cg >> 7;
            int col = (cg & 127) + 2 * q;
            uint32_t* out = (mat == 0) ? g_q : (mat == 1) ? g_k : g_v;
            int r0 = row0 + rg * 32 + mt * 16 + g;
            uint2 lo = make_uint2(f2tf(acc[mt][nt][0]), f2tf(acc[mt][nt][1]));
            *(uint2*)&out[(size_t)r0 * HH + col] = lo;
            uint2 hi = make_uint2(f2tf(acc[mt][nt][2]), f2tf(acc[mt][nt][3]));
            *(uint2*)&out[(size_t)(r0 + 8) * HH + col] = hi;
        }
}

// ---------------------------------------------------------------------------
// Flash attention (causal). R6 structure (best measured): 256-thread block,
// two independent 128-thread halves (q-tiles p and 31-p), named barriers.
// K stored k-interleaved (0,4,1,5,2,6,3,7 per 8-group) -> B-pair = LDS.64.
// ---------------------------------------------------------------------------
#define HALF_WORDS (2 * 64 * LDT)   // K + V tiles for one half

__global__ __launch_bounds__(256, 1) void flash_kernel(float* __restrict__ out)
{
    extern __shared__ uint32_t sm[];

    const int tid  = threadIdx.x;
    const int half = tid >> 7;            // 0 or 1
    const int tid_h = tid & 127;
    const int hw   = (tid >> 5) & 3;      // warp within half
    const int lane = tid & 31;
    const int g = lane >> 2, q = lane & 3;

    const int p  = blockIdx.x;            // 0..15
    const int b  = blockIdx.y;
    const int iq = half ? (31 - p) : p;    // q-tile (64 rows)

    uint32_t* sK = sm + half * HALF_WORDS;
    uint32_t* sV = sK + 64 * LDT;

    // ---- Q fragments straight from gmem (once) ----
    const uint32_t* Qg = g_q + ((size_t)b * TT + iq * 64 + hw * 16) * HH;
    uint32_t aQ[16][4];
#pragma unroll
    for (int ks = 0; ks < 16; ks++) {
        int kk = ks * 8;
        aQ[ks][0] = Qg[(size_t)(g)     * HH + kk + q];
        aQ[ks][1] = Qg[(size_t)(g + 8) * HH + kk + q];
        aQ[ks][2] = Qg[(size_t)(g)     * HH + kk + q + 4];
        aQ[ks][3] = Qg[(size_t)(g + 8) * HH + kk + q + 4];
    }

    float o[16][4];
#pragma unroll
    for (int nt = 0; nt < 16; nt++)
#pragma unroll
        for (int i = 0; i < 4; i++) o[nt][i] = 0.f;
    float m0 = -1e30f, m1 = -1e30f, l0 = 0.f, l1 = 0.f;

    const int lr0 = hw * 16 + g;       // local rows within the 64-row q-tile
    const int lr1 = lr0 + 8;

    for (int jt = 0; jt <= iq; jt++) {
        // prior iteration's reads of sK/sV are done
        asm volatile("bar.sync %0, %1;" :: "r"(half + 1), "r"(128) : "memory");

        const uint32_t* Kg = g_k + ((size_t)b * TT + jt * 64) * HH;
        const uint32_t* Vg = g_v + ((size_t)b * TT + jt * 64) * HH;

        // K: 64 rows x 16 groups of 8; interleave k in group: (0,4,1,5,2,6,3,7)
#pragma unroll
        for (int t = 0; t < 8; t++) {
            int cell = tid_h + t * 128;      // 0..1023
            int r = cell >> 4, gr = cell & 15;
            const uint32_t* Kr = Kg + (size_t)r * HH + gr * 8;
            uint4 v = *(const uint4*)(Kr);
            uint4 w = *(const uint4*)(Kr + 4);
            uint32_t* d = &sK[r * LDT + gr * 8];
            *(uint4*)(d)     = make_uint4(v.x, w.x, v.y, w.y);
            *(uint4*)(d + 4) = make_uint4(v.z, w.z, v.w, w.w);
        }
        // V: plain layout
#pragma unroll
        for (int t = 0; t < 16; t++) {
            int idx = tid_h + t * 128;
            int r = idx >> 5, c4 = (idx & 31) * 4;
            *(uint4*)&sV[r * LDT + c4] = *(const uint4*)(Vg + (size_t)r * HH + c4);
        }
        asm volatile("bar.sync %0, %1;" :: "r"(half + 1), "r"(128) : "memory");

        // ---- S = Q K^T : warp strip 16 x 64, k=128 ----
        float sc[8][4];
#pragma unroll
        for (int nt = 0; nt < 8; nt++)
#pragma unroll
            for (int i = 0; i < 4; i++) sc[nt][i] = 0.f;

#pragma unroll
        for (int ks = 0; ks < 16; ks++) {
            int kk = ks * 8;
#pragma unroll
            for (int nt = 0; nt < 8; nt++) {
                uint2 bb = *(uint2*)&sK[(nt * 8 + g) * LDT + kk + 2 * q];
                mma8(sc[nt], aQ[ks][0], aQ[ks][1], aQ[ks][2], aQ[ks][3],
                     bb.x, bb.y);
            }
        }

        // scale (+ causal mask only on the diagonal tile jt == iq)
#pragma unroll
        for (int nt = 0; nt < 8; nt++)
#pragma unroll
            for (int i = 0; i < 4; i++) sc[nt][i] *= SCALE;
        if (jt == iq) {
#pragma unroll
            for (int nt = 0; nt < 8; nt++) {
                int c = nt * 8 + 2 * q;
                if (c     > lr0) sc[nt][0] = -1e30f;
                if (c + 1 > lr0) sc[nt][1] = -1e30f;
                if (c     > lr1) sc[nt][2] = -1e30f;
                if (c + 1 > lr1) sc[nt][3] = -1e30f;
            }
        }

        // ---- warp-local online softmax (rows g and g+8) ----
        float mt0 = -1e30f, mt1 = -1e30f;
#pragma unroll
        for (int nt = 0; nt < 8; nt++) {
            mt0 = fmaxf(mt0, fmaxf(sc[nt][0], sc[nt][1]));
            mt1 = fmaxf(mt1, fmaxf(sc[nt][2], sc[nt][3]));
        }
        mt0 = fmaxf(mt0, __shfl_xor_sync(0xFFFFFFFFu, mt0, 1));
        mt0 = fmaxf(mt0, __shfl_xor_sync(0xFFFFFFFFu, mt0, 2));
        mt1 = fmaxf(mt1, __shfl_xor_sync(0xFFFFFFFFu, mt1, 1));
        mt1 = fmaxf(mt1, __shfl_xor_sync(0xFFFFFFFFu, mt1, 2));
        float mn0 = fmaxf(m0, mt0), mn1 = fmaxf(m1, mt1);
        float f0 = __expf(m0 - mn0), f1 = __expf(m1 - mn1);
        m0 = mn0; m1 = mn1;

        float s0 = 0.f, s1 = 0.f;
#pragma unroll
        for (int nt = 0; nt < 8; nt++) {
            sc[nt][0] = __expf(sc[nt][0] - mn0); s0 += sc[nt][0];
            sc[nt][1] = __expf(sc[nt][1] - mn0); s0 += sc[nt][1];
            sc[nt][2] = __expf(sc[nt][2] - mn1); s1 += sc[nt][2];
            sc[nt][3] = __expf(sc[nt][3] - mn1); s1 += sc[nt][3];
        }
        s0 += __shfl_xor_sync(0xFFFFFFFFu, s0, 1);
        s0 += __shfl_xor_sync(0xFFFFFFFFu, s0, 2);
        s1 += __shfl_xor_sync(0xFFFFFFFFu, s1, 1);
        s1 += __shfl_xor_sync(0xFFFFFFFFu, s1, 2);
        l0 = l0 * f0 + s0;
        l1 = l1 * f1 + s1;

#pragma unroll
        for (int nt = 0; nt < 16; nt++) {
            o[nt][0] *= f0; o[nt][1] *= f0;
            o[nt][2] *= f1; o[nt][3] *= f1;
        }

        // ---- O += P V : P from registers via shuffle C->A conversion ----
        const int src1 = (lane & ~3) | (q >> 1);
        const int src2 = src1 + 2;
        const bool odd = (q & 1);
#pragma unroll
        for (int ks = 0; ks < 8; ks++) {
            float t0 = __shfl_sync(0xFFFFFFFFu, sc[ks][0], src1);
            float t1 = __shfl_sync(0xFFFFFFFFu, sc[ks][1], src1);
            float t2 = __shfl_sync(0xFFFFFFFFu, sc[ks][2], src1);
            float t3 = __shfl_sync(0xFFFFFFFFu, sc[ks][3], src1);
            float u0 = __shfl_sync(0xFFFFFFFFu, sc[ks][0], src2);
            float u1 = __shfl_sync(0xFFFFFFFFu, sc[ks][1], src2);
            float u2 = __shfl_sync(0xFFFFFFFFu, sc[ks][2], src2);
            float u3 = __shfl_sync(0xFFFFFFFFu, sc[ks][3], src2);
            uint32_t a0 = f2tf(odd ? t1 : t0);
            uint32_t a1 = f2tf(odd ? t3 : t2);
            uint32_t a2 = f2tf(odd ? u1 : u0);
            uint32_t a3 = f2tf(odd ? u3 : u2);
            int kk = ks * 8;
#pragma unroll
            for (int nt = 0; nt < 16; nt++) {
                uint32_t b0 = sV[(kk + q)     * LDT + nt * 8 + g];
                uint32_t b1 = sV[(kk + q + 4) * LDT + nt * 8 + g];
                mma8(o[nt], a0, a1, a2, a3, b0, b1);
            }
        }
    }

    // ---- epilogue (warp-local) ----
    float il0 = 1.f / l0, il1 = 1.f / l1;
    float* Og = out + ((size_t)b * TT + iq * 64 + hw * 16) * HH;
#pragma unroll
    for (int nt = 0; nt < 16; nt++) {
        int c = nt * 8 + 2 * q;
        float2 lo = make_float2(o[nt][0] * il0, o[nt][1] * il0);
        *(float2*)&Og[(size_t)g * HH + c] = lo;
        float2 hi = make_float2(o[nt][2] * il1, o[nt][3] * il1);
        *(float2*)&Og[(size_t)(g + 8) * HH + c] = hi;
    }
}

// ---------------------------------------------------------------------------
extern "C" void kernel_launch(void* const* d_in, const int* in_sizes, int n_in,
                              void* d_out, int out_size)
{
    const float* x  = (const float*)d_in[0];
    const float* Wk = (const float*)d_in[1];
    const float* Wq = (const float*)d_in[2];
    const float* Wv = (const float*)d_in[3];
    float* out = (float*)d_out;

    const int proj_smem = PROJ_SMEM_WORDS * 4;   // 61440
    (void)cudaFuncSetAttribute(proj_kernel,
                               cudaFuncAttributeMaxDynamicSharedMemorySize,
                               proj_smem);

    const int smem_bytes = 2 * HALF_WORDS * 4;   // 135168
    (void)cudaFuncSetAttribute(flash_kernel,
                               cudaFuncAttributeMaxDynamicSharedMemorySize,
                               smem_bytes);

    proj_kernel<<<BT / 64, 256, proj_smem>>>(x, Wk, Wq, Wv);

    dim3 g2(TT / 128, BB);   // 16 pairs x 8 batches = 128 blocks
    flash_kernel<<<g2, 256, smem_bytes>>>(out);
}

// round 14
// speedup vs baseline: 1.1876x; 1.1876x over previous
#include <cuda_runtime.h>
#include <cstdint>

#define BB 8
#define TT 2048
#define CC 1024
#define HH 128
#define BT (BB*TT)
#define SCALE 0.08838834764831845f

#define PX_LD 36     // proj sX row stride (32 k + 4 pad)
#define PW_LD 136    // proj sW row stride (128 n + 8 pad)
#define LDT 132      // flash K/V row stride (128 + 4)

// q/k/v scratch stored as tf32 bit patterns (static device mem: allowed)
__device__ uint32_t g_q[BT * HH];
__device__ uint32_t g_k[BT * HH];
__device__ uint32_t g_v[BT * HH];

__device__ __forceinline__ uint32_t f2tf(float x) {
    uint32_t r;
    asm("cvt.rna.tf32.f32 %0, %1;" : "=r"(r) : "f"(x));
    return r;
}

// D += A*B, m16n8k8, A row-major 16x8 tf32, B col-major 8x8 tf32, fp32 accum
__device__ __forceinline__ void mma8(float* c, uint32_t a0, uint32_t a1,
                                     uint32_t a2, uint32_t a3,
                                     uint32_t b0, uint32_t b1) {
    asm volatile(
        "mma.sync.aligned.m16n8k8.row.col.f32.tf32.tf32.f32 "
        "{%0,%1,%2,%3},{%4,%5,%6,%7},{%8,%9},{%0,%1,%2,%3};"
        : "+f"(c[0]), "+f"(c[1]), "+f"(c[2]), "+f"(c[3])
        : "r"(a0), "r"(a1), "r"(a2), "r"(a3), "r"(b0), "r"(b1));
}

__device__ __forceinline__ void cpa16(uint32_t saddr, const void* gaddr) {
    asm volatile("cp.async.cg.shared.global [%0], [%1], 16;"
                 :: "r"(saddr), "l"(gaddr) : "memory");
}

// ---------------------------------------------------------------------------
// Projection (exact R6 version — best measured config):
// out[mat] = tf32(x @ W[mat]).  M=16384, K=1024, N=128.
// ---------------------------------------------------------------------------
__global__ __launch_bounds__(256) void proj_kernel(
    const float* __restrict__ x,
    const float* __restrict__ Wk,
    const float* __restrict__ Wq,
    const float* __restrict__ Wv)
{
    __shared__ uint32_t sX[128 * PX_LD];
    __shared__ uint32_t sW[32 * PW_LD];

    const int mat = blockIdx.y;
    const float* W = (mat == 0) ? Wq : (mat == 1) ? Wk : Wv;
    uint32_t* out  = (mat == 0) ? g_q : (mat == 1) ? g_k : g_v;

    const int row0 = blockIdx.x * 128;
    const int tid  = threadIdx.x;
    const int wid  = tid >> 5, lane = tid & 31;
    const int g = lane >> 2, q = lane & 3;
    const int m0 = (wid & 3) * 32;
    const int n0 = (wid >> 2) * 64;

    float acc[2][8][4];
#pragma unroll
    for (int mt = 0; mt < 2; mt++)
#pragma unroll
        for (int nt = 0; nt < 8; nt++)
#pragma unroll
            for (int i = 0; i < 4; i++) acc[mt][nt][i] = 0.f;

    for (int k0 = 0; k0 < CC; k0 += 32) {
#pragma unroll
        for (int t = 0; t < 4; t++) {
            int idx = tid + t * 256;
            int r = idx >> 3, c4 = (idx & 7) * 4;
            float4 xv = *(const float4*)(x + (size_t)(row0 + r) * CC + k0 + c4);
            uint4 u = make_uint4(f2tf(xv.x), f2tf(xv.y), f2tf(xv.z), f2tf(xv.w));
            *(uint4*)&sX[r * PX_LD + c4] = u;
        }
#pragma unroll
        for (int t = 0; t < 4; t++) {
            int idx = tid + t * 256;
            int r = idx >> 5, c4 = (idx & 31) * 4;
            float4 wv = *(const float4*)(W + (size_t)(k0 + r) * HH + c4);
            uint4 u = make_uint4(f2tf(wv.x), f2tf(wv.y), f2tf(wv.z), f2tf(wv.w));
            *(uint4*)&sW[r * PW_LD + c4] = u;
        }
        __syncthreads();

#pragma unroll
        for (int ks = 0; ks < 4; ks++) {
            int kk = ks * 8;
            uint32_t a[2][4];
#pragma unroll
            for (int mt = 0; mt < 2; mt++) {
                int mr = m0 + mt * 16;
                a[mt][0] = sX[(mr + g)     * PX_LD + kk + q];
                a[mt][1] = sX[(mr + g + 8) * PX_LD + kk + q];
                a[mt][2] = sX[(mr + g)     * PX_LD + kk + q + 4];
                a[mt][3] = sX[(mr + g + 8) * PX_LD + kk + q + 4];
            }
#pragma unroll
            for (int nt = 0; nt < 8; nt++) {
                uint32_t b0 = sW[(kk + q)     * PW_LD + n0 + nt * 8 + g];
                uint32_t b1 = sW[(kk + q + 4) * PW_LD + n0 + nt * 8 + g];
                mma8(acc[0][nt], a[0][0], a[0][1], a[0][2], a[0][3], b0, b1);
                mma8(acc[1][nt], a[1][0], a[1][1], a[1][2], a[1][3], b0, b1);
            }
        }
        __syncthreads();
    }

#pragma unroll
    for (int mt = 0; mt < 2; mt++)
#pragma unroll
        for (int nt = 0; nt < 8; nt++) {
            int r0 = row0 + m0 + mt * 16 + g;
            int c  = n0 + nt * 8 + 2 * q;
            uint2 lo = make_uint2(f2tf(acc[mt][nt][0]), f2tf(acc[mt][nt][1]));
            *(uint2*)&out[(size_t)r0 * HH + c] = lo;
            uint2 hi = make_uint2(f2tf(acc[mt][nt][2]), f2tf(acc[mt][nt][3]));
            *(uint2*)&out[(size_t)(r0 + 8) * HH + c] = hi;
        }
}

// ---------------------------------------------------------------------------
// Flash attention (causal). R6 two-half structure + cp.async double-buffered
// 32-row K/V stages: fill(s+1) overlaps compute(s). Plain (non-interleaved)
// smem layout — R12 proved the interleave costs 30us via .64 bank conflicts.
// ---------------------------------------------------------------------------
#define STAGE_WORDS (2 * 32 * LDT)        // K + V, one 32-row stage
#define HALF_WORDS  (2 * STAGE_WORDS)     // two stages
// total dynamic smem = 2 halves * HALF_WORDS * 4 = 135168 B

__global__ __launch_bounds__(256, 1) void flash_kernel(float* __restrict__ out)
{
    extern __shared__ uint32_t sm[];
    const uint32_t smem_u32 =
        (uint32_t)__cvta_generic_to_shared(sm);

    const int tid  = threadIdx.x;
    const int half = tid >> 7;            // 0 or 1
    const int tid_h = tid & 127;
    const int hw   = (tid >> 5) & 3;      // warp within half
    const int lane = tid & 31;
    const int g = lane >> 2, q = lane & 3;

    const int p  = blockIdx.x;            // 0..15
    const int b  = blockIdx.y;
    const int iq = half ? (31 - p) : p;   // q-tile (64 rows)

    uint32_t* hbase = sm + half * HALF_WORDS;
    const uint32_t hbase_u32 = smem_u32 + half * HALF_WORDS * 4;

    // ---- Q fragments straight from gmem (once) ----
    const uint32_t* Qg = g_q + ((size_t)b * TT + iq * 64 + hw * 16) * HH;
    uint32_t aQ[16][4];
#pragma unroll
    for (int ks = 0; ks < 16; ks++) {
        int kk = ks * 8;
        aQ[ks][0] = Qg[(size_t)(g)     * HH + kk + q];
        aQ[ks][1] = Qg[(size_t)(g + 8) * HH + kk + q];
        aQ[ks][2] = Qg[(size_t)(g)     * HH + kk + q + 4];
        aQ[ks][3] = Qg[(size_t)(g + 8) * HH + kk + q + 4];
    }

    float o[16][4];
#pragma unroll
    for (int nt = 0; nt < 16; nt++)
#pragma unroll
        for (int i = 0; i < 4; i++) o[nt][i] = 0.f;
    float m0 = -1e30f, m1 = -1e30f, l0 = 0.f, l1 = 0.f;

    const int lr0 = hw * 16 + g;       // local rows in the 64-row q-tile
    const int lr1 = lr0 + 8;
    const int grow0 = iq * 64 + lr0;
    const int grow1 = grow0 + 8;

    const int nstage = 2 * (iq + 1);   // 32-row kv tiles

    // ---- prologue: fill stage 0 ----
    {
        const uint32_t* Kg = g_k + ((size_t)b * TT) * HH;
        const uint32_t* Vg = g_v + ((size_t)b * TT) * HH;
        uint32_t dK = hbase_u32;                       // stage 0
        uint32_t dV = dK + 32 * LDT * 4;
#pragma unroll
        for (int t = 0; t < 8; t++) {
            int idx = tid_h + t * 128;
            int r = idx >> 5, c4 = (idx & 31) * 4;
            cpa16(dK + (r * LDT + c4) * 4, Kg + (size_t)r * HH + c4);
            cpa16(dV + (r * LDT + c4) * 4, Vg + (size_t)r * HH + c4);
        }
        asm volatile("cp.async.commit_group;" ::: "memory");
    }

    for (int s = 0; s < nstage; s++) {
        // issue fill(s+1) into the other buffer; compute(s-1) readers are
        // done (end-of-iter barrier below ran before anyone reaches here)
        if (s + 1 < nstage) {
            const uint32_t* Kg = g_k + ((size_t)b * TT + (s + 1) * 32) * HH;
            const uint32_t* Vg = g_v + ((size_t)b * TT + (s + 1) * 32) * HH;
            uint32_t dK = hbase_u32 + ((s + 1) & 1) * STAGE_WORDS * 4;
            uint32_t dV = dK + 32 * LDT * 4;
#pragma unroll
            for (int t = 0; t < 8; t++) {
                int idx = tid_h + t * 128;
                int r = idx >> 5, c4 = (idx & 31) * 4;
                cpa16(dK + (r * LDT + c4) * 4, Kg + (size_t)r * HH + c4);
                cpa16(dV + (r * LDT + c4) * 4, Vg + (size_t)r * HH + c4);
            }
            asm volatile("cp.async.commit_group;" ::: "memory");
            asm volatile("cp.async.wait_group 1;" ::: "memory");
        } else {
            asm volatile("cp.async.wait_group 0;" ::: "memory");
        }
        // all threads' fill(s) complete after this barrier
        asm volatile("bar.sync %0, %1;" :: "r"(half + 1), "r"(128) : "memory");

        uint32_t* sKb = hbase + (s & 1) * STAGE_WORDS;
        uint32_t* sVb = sKb + 32 * LDT;

        // ---- S = Q K^T : warp strip 16 x 32, k=128 ----
        float sc[4][4];
#pragma unroll
        for (int nt = 0; nt < 4; nt++)
#pragma unroll
            for (int i = 0; i < 4; i++) sc[nt][i] = 0.f;

#pragma unroll
        for (int ks = 0; ks < 16; ks++) {
            int kk = ks * 8;
#pragma unroll
            for (int nt = 0; nt < 4; nt++) {
                uint32_t b0 = sKb[(nt * 8 + g) * LDT + kk + q];
                uint32_t b1 = sKb[(nt * 8 + g) * LDT + kk + q + 4];
                mma8(sc[nt], aQ[ks][0], aQ[ks][1], aQ[ks][2], aQ[ks][3],
                     b0, b1);
            }
        }

        // scale (+ causal mask on the last two stages of this q-tile)
#pragma unroll
        for (int nt = 0; nt < 4; nt++)
#pragma unroll
            for (int i = 0; i < 4; i++) sc[nt][i] *= SCALE;
        if (s >= 2 * iq) {
#pragma unroll
            for (int nt = 0; nt < 4; nt++) {
                int gc = s * 32 + nt * 8 + 2 * q;
                if (gc     > grow0) sc[nt][0] = -1e30f;
                if (gc + 1 > grow0) sc[nt][1] = -1e30f;
                if (gc     > grow1) sc[nt][2] = -1e30f;
                if (gc + 1 > grow1) sc[nt][3] = -1e30f;
            }
        }

        // ---- warp-local online softmax (rows g and g+8) ----
        float mt0 = -1e30f, mt1 = -1e30f;
#pragma unroll
        for (int nt = 0; nt < 4; nt++) {
            mt0 = fmaxf(mt0, fmaxf(sc[nt][0], sc[nt][1]));
            mt1 = fmaxf(mt1, fmaxf(sc[nt][2], sc[nt][3]));
        }
        mt0 = fmaxf(mt0, __shfl_xor_sync(0xFFFFFFFFu, mt0, 1));
        mt0 = fmaxf(mt0, __shfl_xor_sync(0xFFFFFFFFu, mt0, 2));
        mt1 = fmaxf(mt1, __shfl_xor_sync(0xFFFFFFFFu, mt1, 1));
        mt1 = fmaxf(mt1, __shfl_xor_sync(0xFFFFFFFFu, mt1, 2));
        float mn0 = fmaxf(m0, mt0), mn1 = fmaxf(m1, mt1);
        float f0 = __expf(m0 - mn0), f1 = __expf(m1 - mn1);
        m0 = mn0; m1 = mn1;

        float s0 = 0.f, s1 = 0.f;
#pragma unroll
        for (int nt = 0; nt < 4; nt++) {
            sc[nt][0] = __expf(sc[nt][0] - mn0); s0 += sc[nt][0];
            sc[nt][1] = __expf(sc[nt][1] - mn0); s0 += sc[nt][1];
            sc[nt][2] = __expf(sc[nt][2] - mn1); s1 += sc[nt][2];
            sc[nt][3] = __expf(sc[nt][3] - mn1); s1 += sc[nt][3];
        }
        s0 += __shfl_xor_sync(0xFFFFFFFFu, s0, 1);
        s0 += __shfl_xor_sync(0xFFFFFFFFu, s0, 2);
        s1 += __shfl_xor_sync(0xFFFFFFFFu, s1, 1);
        s1 += __shfl_xor_sync(0xFFFFFFFFu, s1, 2);
        l0 = l0 * f0 + s0;
        l1 = l1 * f1 + s1;

#pragma unroll
        for (int nt = 0; nt < 16; nt++) {
            o[nt][0] *= f0; o[nt][1] *= f0;
            o[nt][2] *= f1; o[nt][3] *= f1;
        }

        // ---- O += P V (16x32 @ 32x128): P via shuffle C->A conversion ----
        const int src1 = (lane & ~3) | (q >> 1);
        const int src2 = src1 + 2;
        const bool odd = (q & 1);
#pragma unroll
        for (int ks = 0; ks < 4; ks++) {
            float t0 = __shfl_sync(0xFFFFFFFFu, sc[ks][0], src1);
            float t1 = __shfl_sync(0xFFFFFFFFu, sc[ks][1], src1);
            float t2 = __shfl_sync(0xFFFFFFFFu, sc[ks][2], src1);
            float t3 = __shfl_sync(0xFFFFFFFFu, sc[ks][3], src1);
            float u0 = __shfl_sync(0xFFFFFFFFu, sc[ks][0], src2);
            float u1 = __shfl_sync(0xFFFFFFFFu, sc[ks][1], src2);
            float u2 = __shfl_sync(0xFFFFFFFFu, sc[ks][2], src2);
            float u3 = __shfl_sync(0xFFFFFFFFu, sc[ks][3], src2);
            uint32_t a0 = f2tf(odd ? t1 : t0);
            uint32_t a1 = f2tf(odd ? t3 : t2);
            uint32_t a2 = f2tf(odd ? u1 : u0);
            uint32_t a3 = f2tf(odd ? u3 : u2);
            int kk = ks * 8;
#pragma unroll
            for (int nt = 0; nt < 16; nt++) {
                uint32_t b0 = sVb[(kk + q)     * LDT + nt * 8 + g];
                uint32_t b1 = sVb[(kk + q + 4) * LDT + nt * 8 + g];
                mma8(o[nt], a0, a1, a2, a3, b0, b1);
            }
        }

        // compute(s) done before anyone overwrites buffer s&1 with fill(s+2)
        asm volatile("bar.sync %0, %1;" :: "r"(half + 1), "r"(128) : "memory");
    }

    // ---- epilogue (warp-local) ----
    float il0 = 1.f / l0, il1 = 1.f / l1;
    float* Og = out + ((size_t)b * TT + iq * 64 + hw * 16) * HH;
#pragma unroll
    for (int nt = 0; nt < 16; nt++) {
        int c = nt * 8 + 2 * q;
        float2 lo = make_float2(o[nt][0] * il0, o[nt][1] * il0);
        *(float2*)&Og[(size_t)g * HH + c] = lo;
        float2 hi = make_float2(o[nt][2] * il1, o[nt][3] * il1);
        *(float2*)&Og[(size_t)(g + 8) * HH + c] = hi;
    }
}

// ---------------------------------------------------------------------------
extern "C" void kernel_launch(void* const* d_in, const int* in_sizes, int n_in,
                              void* d_out, int out_size)
{
    const float* x  = (const float*)d_in[0];
    const float* Wk = (const float*)d_in[1];
    const float* Wq = (const float*)d_in[2];
    const float* Wv = (const float*)d_in[3];
    float* out = (float*)d_out;

    const int smem_bytes = 2 * HALF_WORDS * 4;   // 135168
    (void)cudaFuncSetAttribute(flash_kernel,
                               cudaFuncAttributeMaxDynamicSharedMemorySize,
                               smem_bytes);

    dim3 g1(BT / 128, 3);
    proj_kernel<<<g1, 256>>>(x, Wk, Wq, Wv);

    dim3 g2(TT / 128, BB);   // 16 pairs x 8 batches = 128 blocks
    flash_kernel<<<g2, 256, smem_bytes>>>(out);
}

// round 16
// speedup vs baseline: 1.3801x; 1.1621x over previous
#include <cuda_runtime.h>
#include <cstdint>

#define BB 8
#define TT 2048
#define CC 1024
#define HH 128
#define BT (BB*TT)
#define SCALE 0.08838834764831845f

#define PX_LD 36     // proj sX row stride (32 k + 4 pad)
#define PW_LD 136    // proj sW row stride (128 n + 8 pad)
#define LDT 132      // flash K/V row stride (128 + 4)

// q/k/v scratch stored as tf32 bit patterns (static device mem: allowed)
__device__ uint32_t g_q[BT * HH];
__device__ uint32_t g_k[BT * HH];
__device__ uint32_t g_v[BT * HH];

__device__ __forceinline__ uint32_t f2tf(float x) {
    uint32_t r;
    asm("cvt.rna.tf32.f32 %0, %1;" : "=r"(r) : "f"(x));
    return r;
}

// D += A*B, m16n8k8, A row-major 16x8 tf32, B col-major 8x8 tf32, fp32 accum
__device__ __forceinline__ void mma8(float* c, uint32_t a0, uint32_t a1,
                                     uint32_t a2, uint32_t a3,
                                     uint32_t b0, uint32_t b1) {
    asm volatile(
        "mma.sync.aligned.m16n8k8.row.col.f32.tf32.tf32.f32 "
        "{%0,%1,%2,%3},{%4,%5,%6,%7},{%8,%9},{%0,%1,%2,%3};"
        : "+f"(c[0]), "+f"(c[1]), "+f"(c[2]), "+f"(c[3])
        : "r"(a0), "r"(a1), "r"(a2), "r"(a3), "r"(b0), "r"(b1));
}

__device__ __forceinline__ void cpa16(uint32_t saddr, const void* gaddr) {
    asm volatile("cp.async.cg.shared.global [%0], [%1], 16;"
                 :: "r"(saddr), "l"(gaddr) : "memory");
}

// ---------------------------------------------------------------------------
// Projection v3: same tiling/accumulation as R6/R14 (bitwise-identical out),
// but software-pipelined: LDG tile k+1 into regs during compute of tile k,
// double-buffered smem -> ONE barrier per K-step and no exposed gmem latency.
// ---------------------------------------------------------------------------
#define PROJ_BUF_WORDS (128 * PX_LD + 32 * PW_LD)       // 8960 words
#define PROJ_SMEM_BYTES (2 * PROJ_BUF_WORDS * 4)        // 71680 B (dynamic)

__global__ __launch_bounds__(256) void proj_kernel(
    const float* __restrict__ x,
    const float* __restrict__ Wk,
    const float* __restrict__ Wq,
    const float* __restrict__ Wv)
{
    extern __shared__ uint32_t psm[];

    const int mat = blockIdx.y;
    const float* W = (mat == 0) ? Wq : (mat == 1) ? Wk : Wv;
    uint32_t* out  = (mat == 0) ? g_q : (mat == 1) ? g_k : g_v;

    const int row0 = blockIdx.x * 128;
    const int tid  = threadIdx.x;
    const int wid  = tid >> 5, lane = tid & 31;
    const int g = lane >> 2, q = lane & 3;
    const int m0 = (wid & 3) * 32;
    const int n0 = (wid >> 2) * 64;

    // per-thread load coordinates (fixed across iterations)
    const int xr_r  = tid >> 3, xr_c = (tid & 7) * 4;     // +t*32 rows
    const int wr_r  = tid >> 5, wr_c = (tid & 31) * 4;    // +t*8 rows

    float acc[2][8][4];
#pragma unroll
    for (int mt = 0; mt < 2; mt++)
#pragma unroll
        for (int nt = 0; nt < 8; nt++)
#pragma unroll
            for (int i = 0; i < 4; i++) acc[mt][nt][i] = 0.f;

    float4 xr[4], wr[4];
    // ---- prologue: load K-tile 0 into registers ----
#pragma unroll
    for (int t = 0; t < 4; t++)
        xr[t] = *(const float4*)(x + (size_t)(row0 + xr_r + t * 32) * CC + xr_c);
#pragma unroll
    for (int t = 0; t < 4; t++)
        wr[t] = *(const float4*)(W + (size_t)(wr_r + t * 8) * HH + wr_c);

    int buf = 0;
    for (int k0 = 0; k0 < CC; k0 += 32, buf ^= 1) {
        uint32_t* sX = psm + buf * PROJ_BUF_WORDS;
        uint32_t* sW = sX + 128 * PX_LD;

        // store staged tile (convert fp32 -> tf32 here; same order as before)
#pragma unroll
        for (int t = 0; t < 4; t++) {
            uint4 u = make_uint4(f2tf(xr[t].x), f2tf(xr[t].y),
                                 f2tf(xr[t].z), f2tf(xr[t].w));
            *(uint4*)&sX[(xr_r + t * 32) * PX_LD + xr_c] = u;
        }
#pragma unroll
        for (int t = 0; t < 4; t++) {
            uint4 u = make_uint4(f2tf(wr[t].x), f2tf(wr[t].y),
                                 f2tf(wr[t].z), f2tf(wr[t].w));
            *(uint4*)&sW[(wr_r + t * 8) * PW_LD + wr_c] = u;
        }
        __syncthreads();   // publishes buf; also orders compute(k0-64) before
                           // this iteration's overwrite of the same buffer

        // prefetch K-tile k0+32 while computing (LDGs in flight over mma)
        if (k0 + 32 < CC) {
#pragma unroll
            for (int t = 0; t < 4; t++)
                xr[t] = *(const float4*)(x + (size_t)(row0 + xr_r + t * 32) * CC
                                         + k0 + 32 + xr_c);
#pragma unroll
            for (int t = 0; t < 4; t++)
                wr[t] = *(const float4*)(W + (size_t)(k0 + 32 + wr_r + t * 8) * HH
                                         + wr_c);
        }

#pragma unroll
        for (int ks = 0; ks < 4; ks++) {
            int kk = ks * 8;
            uint32_t a[2][4];
#pragma unroll
            for (int mt = 0; mt < 2; mt++) {
                int mr = m0 + mt * 16;
                a[mt][0] = sX[(mr + g)     * PX_LD + kk + q];
                a[mt][1] = sX[(mr + g + 8) * PX_LD + kk + q];
                a[mt][2] = sX[(mr + g)     * PX_LD + kk + q + 4];
                a[mt][3] = sX[(mr + g + 8) * PX_LD + kk + q + 4];
            }
#pragma unroll
            for (int nt = 0; nt < 8; nt++) {
                uint32_t b0 = sW[(kk + q)     * PW_LD + n0 + nt * 8 + g];
                uint32_t b1 = sW[(kk + q + 4) * PW_LD + n0 + nt * 8 + g];
                mma8(acc[0][nt], a[0][0], a[0][1], a[0][2], a[0][3], b0, b1);
                mma8(acc[1][nt], a[1][0], a[1][1], a[1][2], a[1][3], b0, b1);
            }
        }
    }

#pragma unroll
    for (int mt = 0; mt < 2; mt++)
#pragma unroll
        for (int nt = 0; nt < 8; nt++) {
            int r0 = row0 + m0 + mt * 16 + g;
            int c  = n0 + nt * 8 + 2 * q;
            uint2 lo = make_uint2(f2tf(acc[mt][nt][0]), f2tf(acc[mt][nt][1]));
            *(uint2*)&out[(size_t)r0 * HH + c] = lo;
            uint2 hi = make_uint2(f2tf(acc[mt][nt][2]), f2tf(acc[mt][nt][3]));
            *(uint2*)&out[(size_t)(r0 + 8) * HH + c] = hi;
        }
}

// ---------------------------------------------------------------------------
// Flash attention (causal). UNCHANGED from R14 (109.4us measured):
// two-half structure + cp.async double-buffered 32-row K/V stages.
// ---------------------------------------------------------------------------
#define STAGE_WORDS (2 * 32 * LDT)        // K + V, one 32-row stage
#define HALF_WORDS  (2 * STAGE_WORDS)     // two stages

__global__ __launch_bounds__(256, 1) void flash_kernel(float* __restrict__ out)
{
    extern __shared__ uint32_t sm[];
    const uint32_t smem_u32 =
        (uint32_t)__cvta_generic_to_shared(sm);

    const int tid  = threadIdx.x;
    const int half = tid >> 7;            // 0 or 1
    const int tid_h = tid & 127;
    const int hw   = (tid >> 5) & 3;      // warp within half
    const int lane = tid & 31;
    const int g = lane >> 2, q = lane & 3;

    const int p  = blockIdx.x;            // 0..15
    const int b  = blockIdx.y;
    const int iq = half ? (31 - p) : p;   // q-tile (64 rows)

    uint32_t* hbase = sm + half * HALF_WORDS;
    const uint32_t hbase_u32 = smem_u32 + half * HALF_WORDS * 4;

    // ---- Q fragments straight from gmem (once) ----
    const uint32_t* Qg = g_q + ((size_t)b * TT + iq * 64 + hw * 16) * HH;
    uint32_t aQ[16][4];
#pragma unroll
    for (int ks = 0; ks < 16; ks++) {
        int kk = ks * 8;
        aQ[ks][0] = Qg[(size_t)(g)     * HH + kk + q];
        aQ[ks][1] = Qg[(size_t)(g + 8) * HH + kk + q];
        aQ[ks][2] = Qg[(size_t)(g)     * HH + kk + q + 4];
        aQ[ks][3] = Qg[(size_t)(g + 8) * HH + kk + q + 4];
    }

    float o[16][4];
#pragma unroll
    for (int nt = 0; nt < 16; nt++)
#pragma unroll
        for (int i = 0; i < 4; i++) o[nt][i] = 0.f;
    float m0 = -1e30f, m1 = -1e30f, l0 = 0.f, l1 = 0.f;

    const int lr0 = hw * 16 + g;       // local rows in the 64-row q-tile
    const int lr1 = lr0 + 8;
    const int grow0 = iq * 64 + lr0;
    const int grow1 = grow0 + 8;

    const int nstage = 2 * (iq + 1);   // 32-row kv tiles

    // ---- prologue: fill stage 0 ----
    {
        const uint32_t* Kg = g_k + ((size_t)b * TT) * HH;
        const uint32_t* Vg = g_v + ((size_t)b * TT) * HH;
        uint32_t dK = hbase_u32;                       // stage 0
        uint32_t dV = dK + 32 * LDT * 4;
#pragma unroll
        for (int t = 0; t < 8; t++) {
            int idx = tid_h + t * 128;
            int r = idx >> 5, c4 = (idx & 31) * 4;
            cpa16(dK + (r * LDT + c4) * 4, Kg + (size_t)r * HH + c4);
            cpa16(dV + (r * LDT + c4) * 4, Vg + (size_t)r * HH + c4);
        }
        asm volatile("cp.async.commit_group;" ::: "memory");
    }

    for (int s = 0; s < nstage; s++) {
        if (s + 1 < nstage) {
            const uint32_t* Kg = g_k + ((size_t)b * TT + (s + 1) * 32) * HH;
            const uint32_t* Vg = g_v + ((size_t)b * TT + (s + 1) * 32) * HH;
            uint32_t dK = hbase_u32 + ((s + 1) & 1) * STAGE_WORDS * 4;
            uint32_t dV = dK + 32 * LDT * 4;
#pragma unroll
            for (int t = 0; t < 8; t++) {
                int idx = tid_h + t * 128;
                int r = idx >> 5, c4 = (idx & 31) * 4;
                cpa16(dK + (r * LDT + c4) * 4, Kg + (size_t)r * HH + c4);
                cpa16(dV + (r * LDT + c4) * 4, Vg + (size_t)r * HH + c4);
            }
            asm volatile("cp.async.commit_group;" ::: "memory");
            asm volatile("cp.async.wait_group 1;" ::: "memory");
        } else {
            asm volatile("cp.async.wait_group 0;" ::: "memory");
        }
        asm volatile("bar.sync %0, %1;" :: "r"(half + 1), "r"(128) : "memory");

        uint32_t* sKb = hbase + (s & 1) * STAGE_WORDS;
        uint32_t* sVb = sKb + 32 * LDT;

        // ---- S = Q K^T : warp strip 16 x 32, k=128 ----
        float sc[4][4];
#pragma unroll
        for (int nt = 0; nt < 4; nt++)
#pragma unroll
            for (int i = 0; i < 4; i++) sc[nt][i] = 0.f;

#pragma unroll
        for (int ks = 0; ks < 16; ks++) {
            int kk = ks * 8;
#pragma unroll
            for (int nt = 0; nt < 4; nt++) {
                uint32_t b0 = sKb[(nt * 8 + g) * LDT + kk + q];
                uint32_t b1 = sKb[(nt * 8 + g) * LDT + kk + q + 4];
                mma8(sc[nt], aQ[ks][0], aQ[ks][1], aQ[ks][2], aQ[ks][3],
                     b0, b1);
            }
        }

        // scale (+ causal mask on the last two stages of this q-tile)
#pragma unroll
        for (int nt = 0; nt < 4; nt++)
#pragma unroll
            for (int i = 0; i < 4; i++) sc[nt][i] *= SCALE;
        if (s >= 2 * iq) {
#pragma unroll
            for (int nt = 0; nt < 4; nt++) {
                int gc = s * 32 + nt * 8 + 2 * q;
                if (gc     > grow0) sc[nt][0] = -1e30f;
                if (gc + 1 > grow0) sc[nt][1] = -1e30f;
                if (gc     > grow1) sc[nt][2] = -1e30f;
                if (gc + 1 > grow1) sc[nt][3] = -1e30f;
            }
        }

        // ---- warp-local online softmax (rows g and g+8) ----
        float mt0 = -1e30f, mt1 = -1e30f;
#pragma unroll
        for (int nt = 0; nt < 4; nt++) {
            mt0 = fmaxf(mt0, fmaxf(sc[nt][0], sc[nt][1]));
            mt1 = fmaxf(mt1, fmaxf(sc[nt][2], sc[nt][3]));
        }
        mt0 = fmaxf(mt0, __shfl_xor_sync(0xFFFFFFFFu, mt0, 1));
        mt0 = fmaxf(mt0, __shfl_xor_sync(0xFFFFFFFFu, mt0, 2));
        mt1 = fmaxf(mt1, __shfl_xor_sync(0xFFFFFFFFu, mt1, 1));
        mt1 = fmaxf(mt1, __shfl_xor_sync(0xFFFFFFFFu, mt1, 2));
        float mn0 = fmaxf(m0, mt0), mn1 = fmaxf(m1, mt1);
        float f0 = __expf(m0 - mn0), f1 = __expf(m1 - mn1);
        m0 = mn0; m1 = mn1;

        float s0 = 0.f, s1 = 0.f;
#pragma unroll
        for (int nt = 0; nt < 4; nt++) {
            sc[nt][0] = __expf(sc[nt][0] - mn0); s0 += sc[nt][0];
            sc[nt][1] = __expf(sc[nt][1] - mn0); s0 += sc[nt][1];
            sc[nt][2] = __expf(sc[nt][2] - mn1); s1 += sc[nt][2];
            sc[nt][3] = __expf(sc[nt][3] - mn1); s1 += sc[nt][3];
        }
        s0 += __shfl_xor_sync(0xFFFFFFFFu, s0, 1);
        s0 += __shfl_xor_sync(0xFFFFFFFFu, s0, 2);
        s1 += __shfl_xor_sync(0xFFFFFFFFu, s1, 1);
        s1 += __shfl_xor_sync(0xFFFFFFFFu, s1, 2);
        l0 = l0 * f0 + s0;
        l1 = l1 * f1 + s1;

#pragma unroll
        for (int nt = 0; nt < 16; nt++) {
            o[nt][0] *= f0; o[nt][1] *= f0;
            o[nt][2] *= f1; o[nt][3] *= f1;
        }

        // ---- O += P V (16x32 @ 32x128): P via shuffle C->A conversion ----
        const int src1 = (lane & ~3) | (q >> 1);
        const int src2 = src1 + 2;
        const bool odd = (q & 1);
#pragma unroll
        for (int ks = 0; ks < 4; ks++) {
            float t0 = __shfl_sync(0xFFFFFFFFu, sc[ks][0], src1);
            float t1 = __shfl_sync(0xFFFFFFFFu, sc[ks][1], src1);
            float t2 = __shfl_sync(0xFFFFFFFFu, sc[ks][2], src1);
            float t3 = __shfl_sync(0xFFFFFFFFu, sc[ks][3], src1);
            float u0 = __shfl_sync(0xFFFFFFFFu, sc[ks][0], src2);
            float u1 = __shfl_sync(0xFFFFFFFFu, sc[ks][1], src2);
            float u2 = __shfl_sync(0xFFFFFFFFu, sc[ks][2], src2);
            float u3 = __shfl_sync(0xFFFFFFFFu, sc[ks][3], src2);
            uint32_t a0 = f2tf(odd ? t1 : t0);
            uint32_t a1 = f2tf(odd ? t3 : t2);
            uint32_t a2 = f2tf(odd ? u1 : u0);
            uint32_t a3 = f2tf(odd ? u3 : u2);
            int kk = ks * 8;
#pragma unroll
            for (int nt = 0; nt < 16; nt++) {
                uint32_t b0 = sVb[(kk + q)     * LDT + nt * 8 + g];
                uint32_t b1 = sVb[(kk + q + 4) * LDT + nt * 8 + g];
                mma8(o[nt], a0, a1, a2, a3, b0, b1);
            }
        }

        asm volatile("bar.sync %0, %1;" :: "r"(half + 1), "r"(128) : "memory");
    }

    // ---- epilogue (warp-local) ----
    float il0 = 1.f / l0, il1 = 1.f / l1;
    float* Og = out + ((size_t)b * TT + iq * 64 + hw * 16) * HH;
#pragma unroll
    for (int nt = 0; nt < 16; nt++) {
        int c = nt * 8 + 2 * q;
        float2 lo = make_float2(o[nt][0] * il0, o[nt][1] * il0);
        *(float2*)&Og[(size_t)g * HH + c] = lo;
        float2 hi = make_float2(o[nt][2] * il1, o[nt][3] * il1);
        *(float2*)&Og[(size_t)(g + 8) * HH + c] = hi;
    }
}

// ---------------------------------------------------------------------------
extern "C" void kernel_launch(void* const* d_in, const int* in_sizes, int n_in,
                              void* d_out, int out_size)
{
    const float* x  = (const float*)d_in[0];
    const float* Wk = (const float*)d_in[1];
    const float* Wq = (const float*)d_in[2];
    const float* Wv = (const float*)d_in[3];
    float* out = (float*)d_out;

    (void)cudaFuncSetAttribute(proj_kernel,
                               cudaFuncAttributeMaxDynamicSharedMemorySize,
                               PROJ_SMEM_BYTES);

    const int smem_bytes = 2 * HALF_WORDS * 4;   // 135168
    (void)cudaFuncSetAttribute(flash_kernel,
                               cudaFuncAttributeMaxDynamicSharedMemorySize,
                               smem_bytes);

    dim3 g1(BT / 128, 3);
    proj_kernel<<<g1, 256, PROJ_SMEM_BYTES>>>(x, Wk, Wq, Wv);

    dim3 g2(TT / 128, BB);   // 16 pairs x 8 batches = 128 blocks
    flash_kernel<<<g2, 256, smem_bytes>>>(out);
}

// round 17
// speedup vs baseline: 1.4493x; 1.0501x over previous
#include <cuda_runtime.h>
#include <cstdint>

#define BB 8
#define TT 2048
#define CC 1024
#define HH 128
#define BT (BB*TT)
#define SCALE 0.08838834764831845f

#define PX_LD 36     // proj sX row stride (32 k + 4 pad)
#define PW_LD 136    // proj sW row stride (128 n + 8 pad)
#define LDT 132      // flash K/V row stride (128 + 4)

// q/k/v scratch stored as tf32 bit patterns (static device mem: allowed)
__device__ uint32_t g_q[BT * HH];
__device__ uint32_t g_k[BT * HH];
__device__ uint32_t g_v[BT * HH];

__device__ __forceinline__ uint32_t f2tf(float x) {
    uint32_t r;
    asm("cvt.rna.tf32.f32 %0, %1;" : "=r"(r) : "f"(x));
    return r;
}

// D += A*B, m16n8k8, A row-major 16x8 tf32, B col-major 8x8 tf32, fp32 accum
__device__ __forceinline__ void mma8(float* c, uint32_t a0, uint32_t a1,
                                     uint32_t a2, uint32_t a3,
                                     uint32_t b0, uint32_t b1) {
    asm volatile(
        "mma.sync.aligned.m16n8k8.row.col.f32.tf32.tf32.f32 "
        "{%0,%1,%2,%3},{%4,%5,%6,%7},{%8,%9},{%0,%1,%2,%3};"
        : "+f"(c[0]), "+f"(c[1]), "+f"(c[2]), "+f"(c[3])
        : "r"(a0), "r"(a1), "r"(a2), "r"(a3), "r"(b0), "r"(b1));
}

__device__ __forceinline__ void cpa16(uint32_t saddr, const void* gaddr) {
    asm volatile("cp.async.cg.shared.global [%0], [%1], 16;"
                 :: "r"(saddr), "l"(gaddr) : "memory");
}

// ---------------------------------------------------------------------------
// Projection v4: 128-thr CTAs, 2/SM; warp tile 64x64 (1.0 LDS per mma).
// Same pipeline as v3 (reg prefetch + double-buffered smem, 1 barrier/K-step).
// Per-element k-accumulation order unchanged -> q/k/v bitwise identical.
// ---------------------------------------------------------------------------
#define PROJ_BUF_WORDS (128 * PX_LD + 32 * PW_LD)       // 8960 words
#define PROJ_SMEM_BYTES (2 * PROJ_BUF_WORDS * 4)        // 71680 B (dynamic)

__global__ __launch_bounds__(128, 2) void proj_kernel(
    const float* __restrict__ x,
    const float* __restrict__ Wk,
    const float* __restrict__ Wq,
    const float* __restrict__ Wv)
{
    extern __shared__ uint32_t psm[];

    const int mat = blockIdx.y;
    const float* W = (mat == 0) ? Wq : (mat == 1) ? Wk : Wv;
    uint32_t* out  = (mat == 0) ? g_q : (mat == 1) ? g_k : g_v;

    const int row0 = blockIdx.x * 128;
    const int tid  = threadIdx.x;
    const int wid  = tid >> 5, lane = tid & 31;
    const int g = lane >> 2, q = lane & 3;
    const int m0 = (wid & 1) * 64;    // warp rows (64)
    const int n0 = (wid >> 1) * 64;   // warp cols (64)

    // per-thread load coordinates (fixed across iterations), 128 threads
    const int xr_r = tid >> 3, xr_c = (tid & 7) * 4;      // +t*16 rows, t<8
    const int wr_r = tid >> 5, wr_c = (tid & 31) * 4;     // +t*4 rows,  t<8

    float acc[4][8][4];
#pragma unroll
    for (int mt = 0; mt < 4; mt++)
#pragma unroll
        for (int nt = 0; nt < 8; nt++)
#pragma unroll
            for (int i = 0; i < 4; i++) acc[mt][nt][i] = 0.f;

    float4 xr[8], wr[8];
    // ---- prologue: load K-tile 0 into registers ----
#pragma unroll
    for (int t = 0; t < 8; t++)
        xr[t] = *(const float4*)(x + (size_t)(row0 + xr_r + t * 16) * CC + xr_c);
#pragma unroll
    for (int t = 0; t < 8; t++)
        wr[t] = *(const float4*)(W + (size_t)(wr_r + t * 4) * HH + wr_c);

    int buf = 0;
    for (int k0 = 0; k0 < CC; k0 += 32, buf ^= 1) {
        uint32_t* sX = psm + buf * PROJ_BUF_WORDS;
        uint32_t* sW = sX + 128 * PX_LD;

        // store staged tile (fp32 -> tf32 here; same values/order as before)
#pragma unroll
        for (int t = 0; t < 8; t++) {
            uint4 u = make_uint4(f2tf(xr[t].x), f2tf(xr[t].y),
                                 f2tf(xr[t].z), f2tf(xr[t].w));
            *(uint4*)&sX[(xr_r + t * 16) * PX_LD + xr_c] = u;
        }
#pragma unroll
        for (int t = 0; t < 8; t++) {
            uint4 u = make_uint4(f2tf(wr[t].x), f2tf(wr[t].y),
                                 f2tf(wr[t].z), f2tf(wr[t].w));
            *(uint4*)&sW[(wr_r + t * 4) * PW_LD + wr_c] = u;
        }
        __syncthreads();   // publishes buf; orders compute(k0-64) before the
                           // overwrite of this buffer (one barrier per K-step)

        // prefetch K-tile k0+32 while computing
        if (k0 + 32 < CC) {
#pragma unroll
            for (int t = 0; t < 8; t++)
                xr[t] = *(const float4*)(x + (size_t)(row0 + xr_r + t * 16) * CC
                                         + k0 + 32 + xr_c);
#pragma unroll
            for (int t = 0; t < 8; t++)
                wr[t] = *(const float4*)(W + (size_t)(k0 + 32 + wr_r + t * 4) * HH
                                         + wr_c);
        }

#pragma unroll
        for (int ks = 0; ks < 4; ks++) {
            int kk = ks * 8;
            uint32_t a[4][4];
#pragma unroll
            for (int mt = 0; mt < 4; mt++) {
                int mr = m0 + mt * 16;
                a[mt][0] = sX[(mr + g)     * PX_LD + kk + q];
                a[mt][1] = sX[(mr + g + 8) * PX_LD + kk + q];
                a[mt][2] = sX[(mr + g)     * PX_LD + kk + q + 4];
                a[mt][3] = sX[(mr + g + 8) * PX_LD + kk + q + 4];
            }
#pragma unroll
            for (int nt = 0; nt < 8; nt++) {
                uint32_t b0 = sW[(kk + q)     * PW_LD + n0 + nt * 8 + g];
                uint32_t b1 = sW[(kk + q + 4) * PW_LD + n0 + nt * 8 + g];
#pragma unroll
                for (int mt = 0; mt < 4; mt++)
                    mma8(acc[mt][nt], a[mt][0], a[mt][1], a[mt][2], a[mt][3],
                         b0, b1);
            }
        }
    }

#pragma unroll
    for (int mt = 0; mt < 4; mt++)
#pragma unroll
        for (int nt = 0; nt < 8; nt++) {
            int r0 = row0 + m0 + mt * 16 + g;
            int c  = n0 + nt * 8 + 2 * q;
            uint2 lo = make_uint2(f2tf(acc[mt][nt][0]), f2tf(acc[mt][nt][1]));
            *(uint2*)&out[(size_t)r0 * HH + c] = lo;
            uint2 hi = make_uint2(f2tf(acc[mt][nt][2]), f2tf(acc[mt][nt][3]));
            *(uint2*)&out[(size_t)(r0 + 8) * HH + c] = hi;
        }
}

// ---------------------------------------------------------------------------
// Flash attention (causal). UNCHANGED from R14/R16 (109us measured):
// two-half structure + cp.async double-buffered 32-row K/V stages.
// ---------------------------------------------------------------------------
#define STAGE_WORDS (2 * 32 * LDT)        // K + V, one 32-row stage
#define HALF_WORDS  (2 * STAGE_WORDS)     // two stages

__global__ __launch_bounds__(256, 1) void flash_kernel(float* __restrict__ out)
{
    extern __shared__ uint32_t sm[];
    const uint32_t smem_u32 =
        (uint32_t)__cvta_generic_to_shared(sm);

    const int tid  = threadIdx.x;
    const int half = tid >> 7;            // 0 or 1
    const int tid_h = tid & 127;
    const int hw   = (tid >> 5) & 3;      // warp within half
    const int lane = tid & 31;
    const int g = lane >> 2, q = lane & 3;

    const int p  = blockIdx.x;            // 0..15
    const int b  = blockIdx.y;
    const int iq = half ? (31 - p) : p;   // q-tile (64 rows)

    uint32_t* hbase = sm + half * HALF_WORDS;
    const uint32_t hbase_u32 = smem_u32 + half * HALF_WORDS * 4;

    // ---- Q fragments straight from gmem (once) ----
    const uint32_t* Qg = g_q + ((size_t)b * TT + iq * 64 + hw * 16) * HH;
    uint32_t aQ[16][4];
#pragma unroll
    for (int ks = 0; ks < 16; ks++) {
        int kk = ks * 8;
        aQ[ks][0] = Qg[(size_t)(g)     * HH + kk + q];
        aQ[ks][1] = Qg[(size_t)(g + 8) * HH + kk + q];
        aQ[ks][2] = Qg[(size_t)(g)     * HH + kk + q + 4];
        aQ[ks][3] = Qg[(size_t)(g + 8) * HH + kk + q + 4];
    }

    float o[16][4];
#pragma unroll
    for (int nt = 0; nt < 16; nt++)
#pragma unroll
        for (int i = 0; i < 4; i++) o[nt][i] = 0.f;
    float m0 = -1e30f, m1 = -1e30f, l0 = 0.f, l1 = 0.f;

    const int lr0 = hw * 16 + g;       // local rows in the 64-row q-tile
    const int lr1 = lr0 + 8;
    const int grow0 = iq * 64 + lr0;
    const int grow1 = grow0 + 8;

    const int nstage = 2 * (iq + 1);   // 32-row kv tiles

    // ---- prologue: fill stage 0 ----
    {
        const uint32_t* Kg = g_k + ((size_t)b * TT) * HH;
        const uint32_t* Vg = g_v + ((size_t)b * TT) * HH;
        uint32_t dK = hbase_u32;                       // stage 0
        uint32_t dV = dK + 32 * LDT * 4;
#pragma unroll
        for (int t = 0; t < 8; t++) {
            int idx = tid_h + t * 128;
            int r = idx >> 5, c4 = (idx & 31) * 4;
            cpa16(dK + (r * LDT + c4) * 4, Kg + (size_t)r * HH + c4);
            cpa16(dV + (r * LDT + c4) * 4, Vg + (size_t)r * HH + c4);
        }
        asm volatile("cp.async.commit_group;" ::: "memory");
    }

    for (int s = 0; s < nstage; s++) {
        if (s + 1 < nstage) {
            const uint32_t* Kg = g_k + ((size_t)b * TT + (s + 1) * 32) * HH;
            const uint32_t* Vg = g_v + ((size_t)b * TT + (s + 1) * 32) * HH;
            uint32_t dK = hbase_u32 + ((s + 1) & 1) * STAGE_WORDS * 4;
            uint32_t dV = dK + 32 * LDT * 4;
#pragma unroll
            for (int t = 0; t < 8; t++) {
                int idx = tid_h + t * 128;
                int r = idx >> 5, c4 = (idx & 31) * 4;
                cpa16(dK + (r * LDT + c4) * 4, Kg + (size_t)r * HH + c4);
                cpa16(dV + (r * LDT + c4) * 4, Vg + (size_t)r * HH + c4);
            }
            asm volatile("cp.async.commit_group;" ::: "memory");
            asm volatile("cp.async.wait_group 1;" ::: "memory");
        } else {
            asm volatile("cp.async.wait_group 0;" ::: "memory");
        }
        asm volatile("bar.sync %0, %1;" :: "r"(half + 1), "r"(128) : "memory");

        uint32_t* sKb = hbase + (s & 1) * STAGE_WORDS;
        uint32_t* sVb = sKb + 32 * LDT;

        // ---- S = Q K^T : warp strip 16 x 32, k=128 ----
        float sc[4][4];
#pragma unroll
        for (int nt = 0; nt < 4; nt++)
#pragma unroll
            for (int i = 0; i < 4; i++) sc[nt][i] = 0.f;

#pragma unroll
        for (int ks = 0; ks < 16; ks++) {
            int kk = ks * 8;
#pragma unroll
            for (int nt = 0; nt < 4; nt++) {
                uint32_t b0 = sKb[(nt * 8 + g) * LDT + kk + q];
                uint32_t b1 = sKb[(nt * 8 + g) * LDT + kk + q + 4];
                mma8(sc[nt], aQ[ks][0], aQ[ks][1], aQ[ks][2], aQ[ks][3],
                     b0, b1);
            }
        }

        // scale (+ causal mask on the last two stages of this q-tile)
#pragma unroll
        for (int nt = 0; nt < 4; nt++)
#pragma unroll
            for (int i = 0; i < 4; i++) sc[nt][i] *= SCALE;
        if (s >= 2 * iq) {
#pragma unroll
            for (int nt = 0; nt < 4; nt++) {
                int gc = s * 32 + nt * 8 + 2 * q;
                if (gc     > grow0) sc[nt][0] = -1e30f;
                if (gc + 1 > grow0) sc[nt][1] = -1e30f;
                if (gc     > grow1) sc[nt][2] = -1e30f;
                if (gc + 1 > grow1) sc[nt][3] = -1e30f;
            }
        }

        // ---- warp-local online softmax (rows g and g+8) ----
        float mt0 = -1e30f, mt1 = -1e30f;
#pragma unroll
        for (int nt = 0; nt < 4; nt++) {
            mt0 = fmaxf(mt0, fmaxf(sc[nt][0], sc[nt][1]));
            mt1 = fmaxf(mt1, fmaxf(sc[nt][2], sc[nt][3]));
        }
        mt0 = fmaxf(mt0, __shfl_xor_sync(0xFFFFFFFFu, mt0, 1));
        mt0 = fmaxf(mt0, __shfl_xor_sync(0xFFFFFFFFu, mt0, 2));
        mt1 = fmaxf(mt1, __shfl_xor_sync(0xFFFFFFFFu, mt1, 1));
        mt1 = fmaxf(mt1, __shfl_xor_sync(0xFFFFFFFFu, mt1, 2));
        float mn0 = fmaxf(m0, mt0), mn1 = fmaxf(m1, mt1);
        float f0 = __expf(m0 - mn0), f1 = __expf(m1 - mn1);
        m0 = mn0; m1 = mn1;

        float s0 = 0.f, s1 = 0.f;
#pragma unroll
        for (int nt = 0; nt < 4; nt++) {
            sc[nt][0] = __expf(sc[nt][0] - mn0); s0 += sc[nt][0];
            sc[nt][1] = __expf(sc[nt][1] - mn0); s0 += sc[nt][1];
            sc[nt][2] = __expf(sc[nt][2] - mn1); s1 += sc[nt][2];
            sc[nt][3] = __expf(sc[nt][3] - mn1); s1 += sc[nt][3];
        }
        s0 += __shfl_xor_sync(0xFFFFFFFFu, s0, 1);
        s0 += __shfl_xor_sync(0xFFFFFFFFu, s0, 2);
        s1 += __shfl_xor_sync(0xFFFFFFFFu, s1, 1);
        s1 += __shfl_xor_sync(0xFFFFFFFFu, s1, 2);
        l0 = l0 * f0 + s0;
        l1 = l1 * f1 + s1;

#pragma unroll
        for (int nt = 0; nt < 16; nt++) {
            o[nt][0] *= f0; o[nt][1] *= f0;
            o[nt][2] *= f1; o[nt][3] *= f1;
        }

        // ---- O += P V (16x32 @ 32x128): P via shuffle C->A conversion ----
        const int src1 = (lane & ~3) | (q >> 1);
        const int src2 = src1 + 2;
        const bool odd = (q & 1);
#pragma unroll
        for (int ks = 0; ks < 4; ks++) {
            float t0 = __shfl_sync(0xFFFFFFFFu, sc[ks][0], src1);
            float t1 = __shfl_sync(0xFFFFFFFFu, sc[ks][1], src1);
            float t2 = __shfl_sync(0xFFFFFFFFu, sc[ks][2], src1);
            float t3 = __shfl_sync(0xFFFFFFFFu, sc[ks][3], src1);
            float u0 = __shfl_sync(0xFFFFFFFFu, sc[ks][0], src2);
            float u1 = __shfl_sync(0xFFFFFFFFu, sc[ks][1], src2);
            float u2 = __shfl_sync(0xFFFFFFFFu, sc[ks][2], src2);
            float u3 = __shfl_sync(0xFFFFFFFFu, sc[ks][3], src2);
            uint32_t a0 = f2tf(odd ? t1 : t0);
            uint32_t a1 = f2tf(odd ? t3 : t2);
            uint32_t a2 = f2tf(odd ? u1 : u0);
            uint32_t a3 = f2tf(odd ? u3 : u2);
            int kk = ks * 8;
#pragma unroll
            for (int nt = 0; nt < 16; nt++) {
                uint32_t b0 = sVb[(kk + q)     * LDT + nt * 8 + g];
                uint32_t b1 = sVb[(kk + q + 4) * LDT + nt * 8 + g];
                mma8(o[nt], a0, a1, a2, a3, b0, b1);
            }
        }

        asm volatile("bar.sync %0, %1;" :: "r"(half + 1), "r"(128) : "memory");
    }

    // ---- epilogue (warp-local) ----
    float il0 = 1.f / l0, il1 = 1.f / l1;
    float* Og = out + ((size_t)b * TT + iq * 64 + hw * 16) * HH;
#pragma unroll
    for (int nt = 0; nt < 16; nt++) {
        int c = nt * 8 + 2 * q;
        float2 lo = make_float2(o[nt][0] * il0, o[nt][1] * il0);
        *(float2*)&Og[(size_t)g * HH + c] = lo;
        float2 hi = make_float2(o[nt][2] * il1, o[nt][3] * il1);
        *(float2*)&Og[(size_t)(g + 8) * HH + c] = hi;
    }
}

// ---------------------------------------------------------------------------
extern "C" void kernel_launch(void* const* d_in, const int* in_sizes, int n_in,
                              void* d_out, int out_size)
{
    const float* x  = (const float*)d_in[0];
    const float* Wk = (const float*)d_in[1];
    const float* Wq = (const float*)d_in[2];
    const float* Wv = (const float*)d_in[3];
    float* out = (float*)d_out;

    (void)cudaFuncSetAttribute(proj_kernel,
                               cudaFuncAttributeMaxDynamicSharedMemorySize,
                               PROJ_SMEM_BYTES);

    const int smem_bytes = 2 * HALF_WORDS * 4;   // 135168
    (void)cudaFuncSetAttribute(flash_kernel,
                               cudaFuncAttributeMaxDynamicSharedMemorySize,
                               smem_bytes);

    dim3 g1(BT / 128, 3);
    proj_kernel<<<g1, 128, PROJ_SMEM_BYTES>>>(x, Wk, Wq, Wv);

    dim3 g2(TT / 128, BB);   // 16 pairs x 8 batches = 128 blocks
    flash_kernel<<<g2, 256, smem_bytes>>>(out);
}